// round 1
// baseline (speedup 1.0000x reference)
#include <cuda_runtime.h>

#define BB 4
#define SS 32
#define HH 8
#define LL 128
#define DD 512
#define DII 2048
#define NBS  (BB*SS)      // 128
#define NROW (BB*SS*HH)   // 1024

// Scratch (no allocation allowed in kernel_launch)
__device__ float g_ax[NROW*DD];   // attn @ x           (2 MB)
__device__ float g_o [NROW*DD];   // post-LN attn out   (2 MB)
__device__ float g_h [NROW*DII];  // FFN hidden         (8 MB)
__device__ float g_t [NROW*DD];   // pre-LN temp        (2 MB)

// ---------------------------------------------------------------------------
// Kernel A: attention logits + mask + softmax + (attn @ x), one CTA per (b,s)
// ---------------------------------------------------------------------------
__global__ __launch_bounds__(256) void attn_ax_kernel(
    const float* __restrict__ x, const int* __restrict__ mask,
    const float* __restrict__ w, float* __restrict__ attn_out,
    float* __restrict__ ax)
{
    __shared__ float sAttn[HH][LL];
    const int bs = blockIdx.x;
    const float* xb = x + (size_t)bs * LL * DD;
    const int tid = threadIdx.x, warp = tid >> 5, lane = tid & 31;

    // ---- stage 1: logits[h][l] = x[l,:] . w[h,l,:] ----
    for (int l = warp; l < LL; l += 8) {
        const float* xr = xb + l * DD;
        const float* wr = w + (size_t)l * DD;
        float acc[HH];
        #pragma unroll
        for (int h = 0; h < HH; h++) acc[h] = 0.f;
        for (int d = lane; d < DD; d += 32) {
            float xv = xr[d];
            #pragma unroll
            for (int h = 0; h < HH; h++)
                acc[h] = fmaf(xv, wr[(size_t)h * LL * DD + d], acc[h]);
        }
        #pragma unroll
        for (int h = 0; h < HH; h++) {
            float v = acc[h];
            #pragma unroll
            for (int off = 16; off; off >>= 1)
                v += __shfl_down_sync(0xffffffffu, v, off);
            if (lane == 0) sAttn[h][l] = v;
        }
    }
    __syncthreads();

    // ---- softmax: warp h owns head h ----
    if (warp < HH) {
        const float invT = 0.0441941738241592f; // 1/sqrt(512)
        const int h = warp;
        float vals[4];
        float mx = -3.4e38f;
        #pragma unroll
        for (int i = 0; i < 4; i++) {
            int l = lane + 32 * i;
            float lg = sAttn[h][l] * invT;
            if (mask[bs * LL + l] == 0) lg = -1e9f;
            vals[i] = lg;
            mx = fmaxf(mx, lg);
        }
        #pragma unroll
        for (int off = 16; off; off >>= 1)
            mx = fmaxf(mx, __shfl_xor_sync(0xffffffffu, mx, off));
        float sum = 0.f;
        #pragma unroll
        for (int i = 0; i < 4; i++) { vals[i] = __expf(vals[i] - mx); sum += vals[i]; }
        #pragma unroll
        for (int off = 16; off; off >>= 1)
            sum += __shfl_xor_sync(0xffffffffu, sum, off);
        float inv = 1.f / sum;
        #pragma unroll
        for (int i = 0; i < 4; i++) {
            int l = lane + 32 * i;
            float a = vals[i] * inv;
            sAttn[h][l] = a;
            if (attn_out) attn_out[(size_t)(bs * HH + h) * LL + l] = a;
        }
    }
    __syncthreads();

    // ---- stage 2: ax[h][d] = sum_l attn[h][l] * x[l][d] ----
    const int d0 = tid, d1 = tid + 256;
    float a0[HH], a1[HH];
    #pragma unroll
    for (int h = 0; h < HH; h++) { a0[h] = 0.f; a1[h] = 0.f; }
    for (int l = 0; l < LL; l++) {
        float x0 = xb[l * DD + d0];
        float x1 = xb[l * DD + d1];
        #pragma unroll
        for (int h = 0; h < HH; h++) {
            float a = sAttn[h][l];
            a0[h] = fmaf(a, x0, a0[h]);
            a1[h] = fmaf(a, x1, a1[h]);
        }
    }
    #pragma unroll
    for (int h = 0; h < HH; h++) {
        ax[((size_t)bs * HH + h) * DD + d0] = a0[h];
        ax[((size_t)bs * HH + h) * DD + d1] = a1[h];
    }
}

// ---------------------------------------------------------------------------
// GEMM: C[M,N] = A[M,K] @ B[N,K]^T  (+bias, +ReLU, +residual), 256 threads
// Requires BM*BK/4 == 256 and BN*BK/4 == 256.
// ---------------------------------------------------------------------------
template<int BM, int BN, int BK, int TM, int TN, bool RELU, bool RES>
__global__ __launch_bounds__(256) void gemm_nt(
    const float* __restrict__ A, const float* __restrict__ B,
    const float* __restrict__ bias, const float* __restrict__ res,
    float* __restrict__ C, int M, int N, int K)
{
    __shared__ float As[BK][BM];
    __shared__ float Bs[BK][BN];
    const int bm = blockIdx.y * BM, bn = blockIdx.x * BN;
    const int tid = threadIdx.x;
    constexpr int TX = BN / TN;
    const int tx = tid % TX, ty = tid / TX;
    constexpr int KQ = BK / 4;
    const int lr = tid / KQ;
    const int lk = (tid % KQ) * 4;

    float acc[TM][TN];
    #pragma unroll
    for (int i = 0; i < TM; i++)
        #pragma unroll
        for (int j = 0; j < TN; j++) acc[i][j] = 0.f;

    for (int k0 = 0; k0 < K; k0 += BK) {
        float4 a4 = *(const float4*)(A + (size_t)(bm + lr) * K + k0 + lk);
        As[lk + 0][lr] = a4.x; As[lk + 1][lr] = a4.y;
        As[lk + 2][lr] = a4.z; As[lk + 3][lr] = a4.w;
        float4 b4 = *(const float4*)(B + (size_t)(bn + lr) * K + k0 + lk);
        Bs[lk + 0][lr] = b4.x; Bs[lk + 1][lr] = b4.y;
        Bs[lk + 2][lr] = b4.z; Bs[lk + 3][lr] = b4.w;
        __syncthreads();
        #pragma unroll
        for (int k = 0; k < BK; k++) {
            float rm[TM], rn[TN];
            #pragma unroll
            for (int i = 0; i < TM; i++) rm[i] = As[k][ty * TM + i];
            #pragma unroll
            for (int j = 0; j < TN; j++) rn[j] = Bs[k][tx * TN + j];
            #pragma unroll
            for (int i = 0; i < TM; i++)
                #pragma unroll
                for (int j = 0; j < TN; j++)
                    acc[i][j] = fmaf(rm[i], rn[j], acc[i][j]);
        }
        __syncthreads();
    }

    #pragma unroll
    for (int i = 0; i < TM; i++) {
        int m = bm + ty * TM + i;
        #pragma unroll
        for (int j = 0; j < TN; j++) {
            int n = bn + tx * TN + j;
            float v = acc[i][j];
            if (bias) v += bias[n];
            if (RELU) v = fmaxf(v, 0.f);
            if (RES)  v += res[(size_t)m * N + n];
            C[(size_t)m * N + n] = v;
        }
    }
}

// ---------------------------------------------------------------------------
// LayerNorm over D=512, one CTA per row, 256 threads (2 elems/thread)
// ---------------------------------------------------------------------------
__device__ __forceinline__ float block_sum(float v, float* red)
{
    const int lane = threadIdx.x & 31, warp = threadIdx.x >> 5;
    #pragma unroll
    for (int off = 16; off; off >>= 1)
        v += __shfl_xor_sync(0xffffffffu, v, off);
    if (lane == 0) red[warp] = v;
    __syncthreads();
    if (warp == 0) {
        float s = (lane < 8) ? red[lane] : 0.f;
        #pragma unroll
        for (int off = 4; off; off >>= 1)
            s += __shfl_xor_sync(0xffffffffu, s, off);
        if (lane == 0) red[0] = s;
    }
    __syncthreads();
    float rv = red[0];
    __syncthreads();
    return rv;
}

__global__ __launch_bounds__(256) void ln_kernel(
    const float* __restrict__ in, const float* __restrict__ g,
    const float* __restrict__ b, float* __restrict__ out)
{
    __shared__ float red[8];
    const int row = blockIdx.x, tid = threadIdx.x;
    const float* r = in + (size_t)row * DD;
    float v0 = r[tid], v1 = r[tid + 256];
    float mu = block_sum(v0 + v1, red) * (1.f / DD);
    float e0 = v0 - mu, e1 = v1 - mu;
    float var = block_sum(e0 * e0 + e1 * e1, red) * (1.f / DD);
    float inv = rsqrtf(var + 1e-6f);
    out[(size_t)row * DD + tid]       = e0 * inv * g[tid] + b[tid];
    out[(size_t)row * DD + tid + 256] = e1 * inv * g[tid + 256] + b[tid + 256];
}

// ---------------------------------------------------------------------------
extern "C" void kernel_launch(void* const* d_in, const int* in_sizes, int n_in,
                              void* d_out, int out_size)
{
    const float* x    = (const float*)d_in[0];
    const int*   mask = (const int*)  d_in[1];
    const float* w    = (const float*)d_in[2];
    const float* v_w  = (const float*)d_in[3];
    const float* ln_g = (const float*)d_in[4];
    const float* ln_b = (const float*)d_in[5];
    const float* w1   = (const float*)d_in[6];
    const float* b1   = (const float*)d_in[7];
    const float* w2   = (const float*)d_in[8];
    const float* b2   = (const float*)d_in[9];
    const float* fg   = (const float*)d_in[10];
    const float* fb   = (const float*)d_in[11];

    float *ax, *o, *hb, *t;
    cudaGetSymbolAddress((void**)&ax, g_ax);
    cudaGetSymbolAddress((void**)&o,  g_o);
    cudaGetSymbolAddress((void**)&hb, g_h);
    cudaGetSymbolAddress((void**)&t,  g_t);

    float* y_out = (float*)d_out;
    float* attn_out = (out_size >= NROW * DD + NROW * LL) ? (y_out + NROW * DD)
                                                          : nullptr;

    // attn + softmax + attn@x
    attn_ax_kernel<<<NBS, 256>>>(x, mask, w, attn_out, ax);
    // (attn@x) @ v_w^T  -> t  (1024 x 512 x 512)
    gemm_nt<64,64,16,4,4,false,false><<<dim3(DD/64, NROW/64), 256>>>(
        ax, v_w, nullptr, nullptr, t, NROW, DD, DD);
    // LayerNorm -> o
    ln_kernel<<<NROW, 256>>>(t, ln_g, ln_b, o);
    // h = relu(o @ w1^T + b1)   (1024 x 2048 x 512)
    gemm_nt<128,128,8,8,8,true,false><<<dim3(DII/128, NROW/128), 256>>>(
        o, w1, b1, nullptr, hb, NROW, DII, DD);
    // t = h @ w2^T + b2 + o     (1024 x 512 x 2048)
    gemm_nt<64,64,16,4,4,false,true><<<dim3(DD/64, NROW/64), 256>>>(
        hb, w2, b2, o, t, NROW, DD, DII);
    // final LayerNorm -> y
    ln_kernel<<<NROW, 256>>>(t, fg, fb, y_out);
}

// round 3
// speedup vs baseline: 2.0042x; 2.0042x over previous
#include <cuda_runtime.h>
#include <cuda_bf16.h>
#include <cstdint>

#define HHn 8
#define LLn 128
#define DDn 512
#define DIn 2048
#define NBS 128
#define NROW 1024

// ---------------- scratch (device globals; no allocation allowed) ----------
__device__ float g_t  [NROW*DDn];
__device__ float g_o  [NROW*DDn];
__device__ __nv_bfloat16 g_axh[NROW*DDn];
__device__ __nv_bfloat16 g_axl[NROW*DDn];
__device__ __nv_bfloat16 g_oh [NROW*DDn];
__device__ __nv_bfloat16 g_ol [NROW*DDn];
__device__ __nv_bfloat16 g_hh [NROW*DIn];
__device__ __nv_bfloat16 g_hl [NROW*DIn];
__device__ __nv_bfloat16 g_vwh[DDn*DDn];
__device__ __nv_bfloat16 g_vwl[DDn*DDn];
__device__ __nv_bfloat16 g_w1h[DIn*DDn];
__device__ __nv_bfloat16 g_w1l[DIn*DDn];
__device__ __nv_bfloat16 g_w2h[DDn*DIn];
__device__ __nv_bfloat16 g_w2l[DDn*DIn];

// ---------------- helpers ---------------------------------------------------
__device__ __forceinline__ uint32_t smem_u32(const void* p) {
    uint32_t a;
    asm("{ .reg .u64 t; cvta.to.shared.u64 t, %1; cvt.u32.u64 %0, t; }"
        : "=r"(a) : "l"(p));
    return a;
}
__device__ __forceinline__ void bsplit(float v, __nv_bfloat16& h, __nv_bfloat16& l) {
    h = __float2bfloat16(v);
    l = __float2bfloat16(v - __bfloat162float(h));
}

#define CPA16(dst, src) \
    asm volatile("cp.async.cg.shared.global [%0], [%1], 16;" \
                 :: "r"(dst), "l"(src) : "memory")
#define CPA_COMMIT() asm volatile("cp.async.commit_group;" ::: "memory")
#define CPA_WAIT0()  asm volatile("cp.async.wait_group 0;" ::: "memory")

#define LDSM4(r, addr) \
    asm volatile("ldmatrix.sync.aligned.m8n8.x4.shared.b16 {%0,%1,%2,%3}, [%4];" \
                 : "=r"((r)[0]), "=r"((r)[1]), "=r"((r)[2]), "=r"((r)[3]) \
                 : "r"(addr))

#define MMA_BF16(c, a, b) \
    asm volatile("mma.sync.aligned.m16n8k16.row.col.f32.bf16.bf16.f32 " \
        "{%0,%1,%2,%3}, {%4,%5,%6,%7}, {%8,%9}, {%0,%1,%2,%3};" \
        : "+f"((c)[0]), "+f"((c)[1]), "+f"((c)[2]), "+f"((c)[3]) \
        : "r"((a)[0]), "r"((a)[1]), "r"((a)[2]), "r"((a)[3]), \
          "r"((b)[0]), "r"((b)[1]))

// smem tile layout: row-major [rows][32 bf16] = 64B/row, 4 chunks of 16B.
// swizzled chunk = c ^ ((row>>1)&3)  -> conflict-free ldmatrix & cp.async.
__device__ __forceinline__ uint32_t tile_off(int row, int chunk) {
    return (uint32_t)(row * 64 + ((chunk ^ ((row >> 1) & 3)) << 4));
}

// ---------------------------------------------------------------------------
// HMMA split-bf16 GEMM: C[M,N] = A[M,K] @ B[N,K]^T (+bias,+relu,+res)
// BN==BM; BK=32. Double-buffered cp.async pipeline.
// ---------------------------------------------------------------------------
template<int BM, int WM, int WN, bool RELU, bool RES, bool OSPLIT>
__global__ __launch_bounds__(WM*WN*32, 1) void gemm_mma(
    const __nv_bfloat16* __restrict__ Ah, const __nv_bfloat16* __restrict__ Al,
    const __nv_bfloat16* __restrict__ Bh, const __nv_bfloat16* __restrict__ Bl,
    const float* __restrict__ bias, const float* __restrict__ res,
    float* __restrict__ C, __nv_bfloat16* __restrict__ Ch,
    __nv_bfloat16* __restrict__ Cl, int M, int N, int K)
{
    constexpr int BN = BM, BK = 32;
    constexpr int THREADS = WM * WN * 32;
    constexpr int ARR_BYTES = BM * 64;          // one split of one operand tile
    constexpr int STAGE = 4 * ARR_BYTES;        // Ah,Al,Bh,Bl
    constexpr int MT = (BM / WM) / 16;
    constexpr int NT = (BN / WN) / 8;
    constexpr int CHUNKS = 4 * BM * 4;          // 16B chunks per stage
    constexpr int CPT = CHUNKS / THREADS;       // chunks per thread

    extern __shared__ __align__(128) char dsm[];
    const uint32_t sb = smem_u32(dsm);

    const int tid = threadIdx.x, wid = tid >> 5, lane = tid & 31;
    const int bm = blockIdx.y * BM, bn = blockIdx.x * BN;
    const int wm = wid / WN, wn = wid % WN;
    const int KT = K / BK;

    auto load_stage = [&](int kt, int s) {
        const uint32_t base = sb + s * STAGE;
        #pragma unroll
        for (int i = 0; i < CPT; i++) {
            int id = tid + i * THREADS;
            int aid = id / (BM * 4);
            int wthin = id % (BM * 4);
            int row = wthin >> 2;
            int ck = wthin & 3;
            const __nv_bfloat16* g;
            if (aid == 0) g = Ah; else if (aid == 1) g = Al;
            else if (aid == 2) g = Bh; else g = Bl;
            int rowbase = (aid < 2) ? bm : bn;
            const __nv_bfloat16* src =
                g + (size_t)(rowbase + row) * K + (size_t)kt * BK + ck * 8;
            uint32_t dst = base + aid * ARR_BYTES + tile_off(row, ck);
            CPA16(dst, src);
        }
        CPA_COMMIT();
    };

    float c[MT][NT][4];
    #pragma unroll
    for (int i = 0; i < MT; i++)
        #pragma unroll
        for (int j = 0; j < NT; j++)
            #pragma unroll
            for (int q = 0; q < 4; q++) c[i][j][q] = 0.f;

    load_stage(0, 0);
    CPA_WAIT0();
    __syncthreads();

    const int aRow0 = wm * (BM / WM);
    const int bRow0 = wn * (BN / WN);

    for (int kt = 0; kt < KT; kt++) {
        if (kt + 1 < KT) load_stage(kt + 1, (kt + 1) & 1);

        const uint32_t base = sb + (kt & 1) * STAGE;
        const uint32_t sAh = base;
        const uint32_t sAl = base + ARR_BYTES;
        const uint32_t sBh = base + 2 * ARR_BYTES;
        const uint32_t sBl = base + 3 * ARR_BYTES;

        #pragma unroll
        for (int ks = 0; ks < 2; ks++) {
            uint32_t aH[MT][4], aL[MT][4];
            #pragma unroll
            for (int mt = 0; mt < MT; mt++) {
                int row = aRow0 + mt * 16 + (lane & 15);
                int ck = ks * 2 + (lane >> 4);
                uint32_t off = tile_off(row, ck);
                LDSM4(aH[mt], sAh + off);
                LDSM4(aL[mt], sAl + off);
            }
            uint32_t bH[NT][2], bL[NT][2];
            #pragma unroll
            for (int p = 0; p < NT / 2; p++) {
                int row = bRow0 + p * 16 + (lane & 7) + ((lane >> 4) << 3);
                int ck = ks * 2 + ((lane >> 3) & 1);
                uint32_t off = tile_off(row, ck);
                uint32_t r[4];
                LDSM4(r, sBh + off);
                bH[2*p][0] = r[0]; bH[2*p][1] = r[1];
                bH[2*p+1][0] = r[2]; bH[2*p+1][1] = r[3];
                LDSM4(r, sBl + off);
                bL[2*p][0] = r[0]; bL[2*p][1] = r[1];
                bL[2*p+1][0] = r[2]; bL[2*p+1][1] = r[3];
            }
            #pragma unroll
            for (int mt = 0; mt < MT; mt++)
                #pragma unroll
                for (int nt = 0; nt < NT; nt++) {
                    MMA_BF16(c[mt][nt], aH[mt], bH[nt]);
                    MMA_BF16(c[mt][nt], aH[mt], bL[nt]);
                    MMA_BF16(c[mt][nt], aL[mt], bH[nt]);
                }
        }
        CPA_WAIT0();
        __syncthreads();
    }

    // ---- epilogue: registers -> global ----
    #pragma unroll
    for (int mt = 0; mt < MT; mt++) {
        #pragma unroll
        for (int nt = 0; nt < NT; nt++) {
            int row = bm + aRow0 + mt * 16 + (lane >> 2);
            int col = bn + bRow0 + nt * 8 + ((lane & 3) << 1);
            #pragma unroll
            for (int half = 0; half < 2; half++) {
                int r = row + half * 8;
                float v0 = c[mt][nt][half * 2 + 0];
                float v1 = c[mt][nt][half * 2 + 1];
                if (bias) { v0 += bias[col]; v1 += bias[col + 1]; }
                if (RELU) { v0 = fmaxf(v0, 0.f); v1 = fmaxf(v1, 0.f); }
                if (RES) {
                    v0 += res[(size_t)r * N + col];
                    v1 += res[(size_t)r * N + col + 1];
                }
                if (OSPLIT) {
                    __nv_bfloat16 h, l;
                    bsplit(v0, h, l);
                    Ch[(size_t)r * N + col] = h; Cl[(size_t)r * N + col] = l;
                    bsplit(v1, h, l);
                    Ch[(size_t)r * N + col + 1] = h; Cl[(size_t)r * N + col + 1] = l;
                } else {
                    C[(size_t)r * N + col] = v0;
                    C[(size_t)r * N + col + 1] = v1;
                }
            }
        }
    }
}

// ---------------------------------------------------------------------------
// Kernel A: attention logits + mask + softmax + (attn @ x) -> split bf16
// ---------------------------------------------------------------------------
__global__ __launch_bounds__(256) void attn_ax_kernel(
    const float* __restrict__ x, const int* __restrict__ mask,
    const float* __restrict__ w, float* __restrict__ attn_out,
    __nv_bfloat16* __restrict__ axh, __nv_bfloat16* __restrict__ axl)
{
    __shared__ float sAttn[HHn][LLn];
    const int bs = blockIdx.x;
    const float* xb = x + (size_t)bs * LLn * DDn;
    const int tid = threadIdx.x, warp = tid >> 5, lane = tid & 31;

    for (int l = warp; l < LLn; l += 8) {
        const float* xr = xb + l * DDn;
        const float* wr = w + (size_t)l * DDn;
        float acc[HHn];
        #pragma unroll
        for (int h = 0; h < HHn; h++) acc[h] = 0.f;
        for (int d = lane; d < DDn; d += 32) {
            float xv = xr[d];
            #pragma unroll
            for (int h = 0; h < HHn; h++)
                acc[h] = fmaf(xv, wr[(size_t)h * LLn * DDn + d], acc[h]);
        }
        #pragma unroll
        for (int h = 0; h < HHn; h++) {
            float v = acc[h];
            #pragma unroll
            for (int off = 16; off; off >>= 1)
                v += __shfl_down_sync(0xffffffffu, v, off);
            if (lane == 0) sAttn[h][l] = v;
        }
    }
    __syncthreads();

    if (warp < HHn) {
        const float invT = 0.0441941738241592f;
        const int h = warp;
        float vals[4], mx = -3.4e38f;
        #pragma unroll
        for (int i = 0; i < 4; i++) {
            int l = lane + 32 * i;
            float lg = sAttn[h][l] * invT;
            if (mask[bs * LLn + l] == 0) lg = -1e9f;
            vals[i] = lg; mx = fmaxf(mx, lg);
        }
        #pragma unroll
        for (int off = 16; off; off >>= 1)
            mx = fmaxf(mx, __shfl_xor_sync(0xffffffffu, mx, off));
        float sum = 0.f;
        #pragma unroll
        for (int i = 0; i < 4; i++) { vals[i] = __expf(vals[i] - mx); sum += vals[i]; }
        #pragma unroll
        for (int off = 16; off; off >>= 1)
            sum += __shfl_xor_sync(0xffffffffu, sum, off);
        float inv = 1.f / sum;
        #pragma unroll
        for (int i = 0; i < 4; i++) {
            int l = lane + 32 * i;
            float a = vals[i] * inv;
            sAttn[h][l] = a;
            if (attn_out) attn_out[(size_t)(bs * HHn + h) * LLn + l] = a;
        }
    }
    __syncthreads();

    const int d0 = tid, d1 = tid + 256;
    float a0[HHn], a1[HHn];
    #pragma unroll
    for (int h = 0; h < HHn; h++) { a0[h] = 0.f; a1[h] = 0.f; }
    for (int l = 0; l < LLn; l++) {
        float x0 = xb[l * DDn + d0];
        float x1 = xb[l * DDn + d1];
        #pragma unroll
        for (int h = 0; h < HHn; h++) {
            float a = sAttn[h][l];
            a0[h] = fmaf(a, x0, a0[h]);
            a1[h] = fmaf(a, x1, a1[h]);
        }
    }
    #pragma unroll
    for (int h = 0; h < HHn; h++) {
        size_t i0 = ((size_t)bs * HHn + h) * DDn + d0;
        size_t i1 = ((size_t)bs * HHn + h) * DDn + d1;
        __nv_bfloat16 hh, ll;
        bsplit(a0[h], hh, ll); axh[i0] = hh; axl[i0] = ll;
        bsplit(a1[h], hh, ll); axh[i1] = hh; axl[i1] = ll;
    }
}

// ---------------------------------------------------------------------------
// Split fp32 -> (bf16 hi, bf16 lo), float4-vectorized
// ---------------------------------------------------------------------------
__global__ __launch_bounds__(256) void split_kernel(
    const float4* __restrict__ in, __nv_bfloat16* __restrict__ hi,
    __nv_bfloat16* __restrict__ lo, int n4)
{
    int i = blockIdx.x * blockDim.x + threadIdx.x;
    if (i >= n4) return;
    float4 v = in[i];
    __nv_bfloat16 h[4], l[4];
    bsplit(v.x, h[0], l[0]); bsplit(v.y, h[1], l[1]);
    bsplit(v.z, h[2], l[2]); bsplit(v.w, h[3], l[3]);
    *(ushort4*)(hi + 4 * (size_t)i) = make_ushort4(
        __bfloat16_as_ushort(h[0]), __bfloat16_as_ushort(h[1]),
        __bfloat16_as_ushort(h[2]), __bfloat16_as_ushort(h[3]));
    *(ushort4*)(lo + 4 * (size_t)i) = make_ushort4(
        __bfloat16_as_ushort(l[0]), __bfloat16_as_ushort(l[1]),
        __bfloat16_as_ushort(l[2]), __bfloat16_as_ushort(l[3]));
}

// ---------------------------------------------------------------------------
// LayerNorm D=512, one CTA/row; optional split bf16 outputs
// ---------------------------------------------------------------------------
__device__ __forceinline__ float block_sum(float v, float* red)
{
    const int lane = threadIdx.x & 31, warp = threadIdx.x >> 5;
    #pragma unroll
    for (int off = 16; off; off >>= 1)
        v += __shfl_xor_sync(0xffffffffu, v, off);
    if (lane == 0) red[warp] = v;
    __syncthreads();
    if (warp == 0) {
        float s = (lane < 8) ? red[lane] : 0.f;
        #pragma unroll
        for (int off = 4; off; off >>= 1)
            s += __shfl_xor_sync(0xffffffffu, s, off);
        if (lane == 0) red[0] = s;
    }
    __syncthreads();
    float rv = red[0];
    __syncthreads();
    return rv;
}

template<bool SPLIT>
__global__ __launch_bounds__(256) void ln_kernel(
    const float* __restrict__ in, const float* __restrict__ g,
    const float* __restrict__ b, float* __restrict__ out,
    __nv_bfloat16* __restrict__ oh, __nv_bfloat16* __restrict__ ol)
{
    __shared__ float red[8];
    const int row = blockIdx.x, tid = threadIdx.x;
    const float* r = in + (size_t)row * DDn;
    float v0 = r[tid], v1 = r[tid + 256];
    float mu = block_sum(v0 + v1, red) * (1.f / DDn);
    float e0 = v0 - mu, e1 = v1 - mu;
    float var = block_sum(e0 * e0 + e1 * e1, red) * (1.f / DDn);
    float inv = rsqrtf(var + 1e-6f);
    float y0 = e0 * inv * g[tid] + b[tid];
    float y1 = e1 * inv * g[tid + 256] + b[tid + 256];
    size_t i0 = (size_t)row * DDn + tid, i1 = i0 + 256;
    out[i0] = y0; out[i1] = y1;
    if (SPLIT) {
        __nv_bfloat16 h, l;
        bsplit(y0, h, l); oh[i0] = h; ol[i0] = l;
        bsplit(y1, h, l); oh[i1] = h; ol[i1] = l;
    }
}

// ---------------------------------------------------------------------------
extern "C" void kernel_launch(void* const* d_in, const int* in_sizes, int n_in,
                              void* d_out, int out_size)
{
    const float* x    = (const float*)d_in[0];
    const int*   mask = (const int*)  d_in[1];
    const float* w    = (const float*)d_in[2];
    const float* v_w  = (const float*)d_in[3];
    const float* ln_g = (const float*)d_in[4];
    const float* ln_b = (const float*)d_in[5];
    const float* w1   = (const float*)d_in[6];
    const float* b1   = (const float*)d_in[7];
    const float* w2   = (const float*)d_in[8];
    const float* b2   = (const float*)d_in[9];
    const float* fg   = (const float*)d_in[10];
    const float* fb   = (const float*)d_in[11];

    float *t, *o;
    __nv_bfloat16 *axh, *axl, *oh, *ol, *hh, *hl;
    __nv_bfloat16 *vwh, *vwl, *w1h, *w1l, *w2h, *w2l;
    cudaGetSymbolAddress((void**)&t,   g_t);
    cudaGetSymbolAddress((void**)&o,   g_o);
    cudaGetSymbolAddress((void**)&axh, g_axh);
    cudaGetSymbolAddress((void**)&axl, g_axl);
    cudaGetSymbolAddress((void**)&oh,  g_oh);
    cudaGetSymbolAddress((void**)&ol,  g_ol);
    cudaGetSymbolAddress((void**)&hh,  g_hh);
    cudaGetSymbolAddress((void**)&hl,  g_hl);
    cudaGetSymbolAddress((void**)&vwh, g_vwh);
    cudaGetSymbolAddress((void**)&vwl, g_vwl);
    cudaGetSymbolAddress((void**)&w1h, g_w1h);
    cudaGetSymbolAddress((void**)&w1l, g_w1l);
    cudaGetSymbolAddress((void**)&w2h, g_w2h);
    cudaGetSymbolAddress((void**)&w2l, g_w2l);

    float* y_out = (float*)d_out;
    float* attn_out = (out_size >= NROW * DDn + NROW * LLn)
                        ? (y_out + NROW * DDn) : nullptr;

    constexpr int SM128 = 2 * 4 * 128 * 64;  // 65536
    constexpr int SM64  = 2 * 4 * 64 * 64;   // 32768
    cudaFuncSetAttribute(gemm_mma<64, 2, 2, false, false, false>,
                         cudaFuncAttributeMaxDynamicSharedMemorySize, SM64);
    cudaFuncSetAttribute(gemm_mma<128, 2, 4, true, false, true>,
                         cudaFuncAttributeMaxDynamicSharedMemorySize, SM128);
    cudaFuncSetAttribute(gemm_mma<64, 2, 2, false, true, false>,
                         cudaFuncAttributeMaxDynamicSharedMemorySize, SM64);

    // split weights to bf16 hi/lo
    split_kernel<<<(DDn*DDn/4 + 255)/256, 256>>>(
        (const float4*)v_w, vwh, vwl, DDn*DDn/4);
    split_kernel<<<(DIn*DDn/4 + 255)/256, 256>>>(
        (const float4*)w1, w1h, w1l, DIn*DDn/4);
    split_kernel<<<(DDn*DIn/4 + 255)/256, 256>>>(
        (const float4*)w2, w2h, w2l, DDn*DIn/4);

    // attention + softmax + attn@x (split bf16 outputs)
    attn_ax_kernel<<<NBS, 256>>>(x, mask, w, attn_out, axh, axl);

    // t = ax @ v_w^T   (1024 x 512 x 512)
    gemm_mma<64, 2, 2, false, false, false>
        <<<dim3(DDn/64, NROW/64), 128, SM64>>>(
        axh, axl, vwh, vwl, nullptr, nullptr, t, nullptr, nullptr,
        NROW, DDn, DDn);

    // o = LN(t) (+ split)
    ln_kernel<true><<<NROW, 256>>>(t, ln_g, ln_b, o, oh, ol);

    // h = relu(o @ w1^T + b1), split output  (1024 x 2048 x 512)
    gemm_mma<128, 2, 4, true, false, true>
        <<<dim3(DIn/128, NROW/128), 256, SM128>>>(
        oh, ol, w1h, w1l, b1, nullptr, nullptr, hh, hl,
        NROW, DIn, DDn);

    // t = h @ w2^T + b2 + o  (1024 x 512 x 2048)
    gemm_mma<64, 2, 2, false, true, false>
        <<<dim3(DDn/64, NROW/64), 128, SM64>>>(
        hh, hl, w2h, w2l, b2, o, t, nullptr, nullptr,
        NROW, DDn, DIn);

    // y = LN(t)
    ln_kernel<false><<<NROW, 256>>>(t, fg, fb, y_out, nullptr, nullptr);
}

// round 4
// speedup vs baseline: 2.7471x; 1.3707x over previous
#include <cuda_runtime.h>
#include <cuda_bf16.h>
#include <cstdint>

#define HHn 8
#define LLn 128
#define DDn 512
#define DIn 2048
#define NBS 128
#define NROW 1024

typedef unsigned long long u64;

// ---------------- scratch (device globals; no allocation allowed) ----------
__device__ float g_t  [NROW*DDn];
__device__ float g_o  [NROW*DDn];
__device__ float g_logits[NROW*LLn];
__device__ float g_attn  [NROW*LLn];
__device__ __nv_bfloat16 g_axh[NROW*DDn];
__device__ __nv_bfloat16 g_axl[NROW*DDn];
__device__ __nv_bfloat16 g_oh [NROW*DDn];
__device__ __nv_bfloat16 g_ol [NROW*DDn];
__device__ __nv_bfloat16 g_hh [NROW*DIn];
__device__ __nv_bfloat16 g_hl [NROW*DIn];
__device__ __nv_bfloat16 g_vwh[DDn*DDn];
__device__ __nv_bfloat16 g_vwl[DDn*DDn];
__device__ __nv_bfloat16 g_w1h[DIn*DDn];
__device__ __nv_bfloat16 g_w1l[DIn*DDn];
__device__ __nv_bfloat16 g_w2h[DDn*DIn];
__device__ __nv_bfloat16 g_w2l[DDn*DIn];

// ---------------- helpers ---------------------------------------------------
__device__ __forceinline__ uint32_t smem_u32(const void* p) {
    uint32_t a;
    asm("{ .reg .u64 t; cvta.to.shared.u64 t, %1; cvt.u32.u64 %0, t; }"
        : "=r"(a) : "l"(p));
    return a;
}
__device__ __forceinline__ void bsplit(float v, __nv_bfloat16& h, __nv_bfloat16& l) {
    h = __float2bfloat16(v);
    l = __float2bfloat16(v - __bfloat162float(h));
}
__device__ __forceinline__ void fma2(u64 &d, u64 a, u64 b) {
    asm("fma.rn.f32x2 %0, %1, %2, %0;" : "+l"(d) : "l"(a), "l"(b));
}
__device__ __forceinline__ u64 pk2(float a, float b) {
    u64 r; asm("mov.b64 %0, {%1,%2};" : "=l"(r) : "f"(a), "f"(b)); return r;
}
__device__ __forceinline__ float2 upk2(u64 v) {
    float2 r; asm("mov.b64 {%0,%1}, %2;" : "=f"(r.x), "=f"(r.y) : "l"(v)); return r;
}

#define CPA16(dst, src) \
    asm volatile("cp.async.cg.shared.global [%0], [%1], 16;" \
                 :: "r"(dst), "l"(src) : "memory")
#define CPA_COMMIT() asm volatile("cp.async.commit_group;" ::: "memory")
#define CPA_WAIT0()  asm volatile("cp.async.wait_group 0;" ::: "memory")

#define LDSM4(r, addr) \
    asm volatile("ldmatrix.sync.aligned.m8n8.x4.shared.b16 {%0,%1,%2,%3}, [%4];" \
                 : "=r"((r)[0]), "=r"((r)[1]), "=r"((r)[2]), "=r"((r)[3]) \
                 : "r"(addr))

#define MMA_BF16(c, a, b) \
    asm volatile("mma.sync.aligned.m16n8k16.row.col.f32.bf16.bf16.f32 " \
        "{%0,%1,%2,%3}, {%4,%5,%6,%7}, {%8,%9}, {%0,%1,%2,%3};" \
        : "+f"((c)[0]), "+f"((c)[1]), "+f"((c)[2]), "+f"((c)[3]) \
        : "r"((a)[0]), "r"((a)[1]), "r"((a)[2]), "r"((a)[3]), \
          "r"((b)[0]), "r"((b)[1]))

__device__ __forceinline__ uint32_t tile_off(int row, int chunk) {
    return (uint32_t)(row * 64 + ((chunk ^ ((row >> 1) & 3)) << 4));
}

// ---------------------------------------------------------------------------
// K1: logits[bs][h][l] = sum_d x[bs,l,d] * w[h,l,d].  One CTA per l.
// ---------------------------------------------------------------------------
__global__ __launch_bounds__(256) void logits_kernel(
    const float* __restrict__ x, const float* __restrict__ w,
    float* __restrict__ logits)
{
    __shared__ __align__(16) float w_s[HHn][DDn];
    const int l = blockIdx.x;
    const int tid = threadIdx.x, warp = tid >> 5, lane = tid & 31;

    #pragma unroll
    for (int i = 0; i < 4; i++) {
        int idx = tid + i * 256;          // float4 units, 1024 total
        int h = idx >> 7, d4 = idx & 127;
        ((float4*)w_s[h])[d4] =
            ((const float4*)(w + ((size_t)(h * LLn + l)) * DDn))[d4];
    }
    __syncthreads();

    const int j  = __brev((unsigned)lane) >> 27;   // value index this lane owns
    const int jb = j >> 3, jh = j & 7;

    for (int q = 0; q < 4; q++) {
        const int bs0 = warp * 16 + q * 4;
        u64 acc[4][HHn];
        #pragma unroll
        for (int b = 0; b < 4; b++)
            #pragma unroll
            for (int h = 0; h < HHn; h++) acc[b][h] = 0ull;

        #pragma unroll
        for (int c = 0; c < 4; c++) {
            const int d4 = c * 32 + lane;          // double2 index within 512 floats
            u64 xp[4][2];
            #pragma unroll
            for (int b = 0; b < 4; b++) {
                double2 xv = ((const double2*)
                    (x + ((size_t)((bs0 + b) * LLn + l)) * DDn))[d4];
                xp[b][0] = __double_as_longlong(xv.x);
                xp[b][1] = __double_as_longlong(xv.y);
            }
            #pragma unroll
            for (int h = 0; h < HHn; h++) {
                double2 wv = ((const double2*)w_s[h])[d4];
                u64 w0 = __double_as_longlong(wv.x);
                u64 w1 = __double_as_longlong(wv.y);
                #pragma unroll
                for (int b = 0; b < 4; b++) {
                    fma2(acc[b][h], xp[b][0], w0);
                    fma2(acc[b][h], xp[b][1], w1);
                }
            }
        }
        float vals[32];
        #pragma unroll
        for (int b = 0; b < 4; b++)
            #pragma unroll
            for (int h = 0; h < HHn; h++) {
                float2 p = upk2(acc[b][h]);
                vals[b * 8 + h] = p.x + p.y;
            }
        // multi-value butterfly: 31 shfl; lane ends owning vals index bitrev5(lane)
        #pragma unroll
        for (int s = 0; s < 5; s++) {
            const int n = 32 >> s;
            const int off = 1 << s;
            const bool up = (lane & off) != 0;
            #pragma unroll
            for (int i = 0; i < (n >> 1); i++) {
                float kept = up ? vals[i + (n >> 1)] : vals[i];
                float sent = up ? vals[i] : vals[i + (n >> 1)];
                float r = __shfl_xor_sync(0xffffffffu, sent, off);
                vals[i] = kept + r;
            }
        }
        logits[((size_t)(bs0 + jb) * HHn + jh) * LLn + l] = vals[0];
    }
}

// ---------------------------------------------------------------------------
// K2: softmax over l per (bs,h) row; warp per row
// ---------------------------------------------------------------------------
__global__ __launch_bounds__(256) void softmax_kernel(
    const float* __restrict__ logits, const int* __restrict__ mask,
    float* __restrict__ attn, float* __restrict__ attn_out)
{
    const int row = blockIdx.x * 8 + (threadIdx.x >> 5);
    const int lane = threadIdx.x & 31;
    const int bs = row >> 3;
    const float invT = 0.0441941738241592f;  // 1/sqrt(512)

    float v[4], mx = -3.4e38f;
    #pragma unroll
    for (int i = 0; i < 4; i++) {
        int l = lane + 32 * i;
        float lg = logits[(size_t)row * LLn + l] * invT;
        if (mask[bs * LLn + l] == 0) lg = -1e9f;
        v[i] = lg; mx = fmaxf(mx, lg);
    }
    #pragma unroll
    for (int off = 16; off; off >>= 1)
        mx = fmaxf(mx, __shfl_xor_sync(0xffffffffu, mx, off));
    float sum = 0.f;
    #pragma unroll
    for (int i = 0; i < 4; i++) { v[i] = __expf(v[i] - mx); sum += v[i]; }
    #pragma unroll
    for (int off = 16; off; off >>= 1)
        sum += __shfl_xor_sync(0xffffffffu, sum, off);
    float inv = 1.f / sum;
    #pragma unroll
    for (int i = 0; i < 4; i++) {
        int l = lane + 32 * i;
        float a = v[i] * inv;
        attn[(size_t)row * LLn + l] = a;
        if (attn_out) attn_out[(size_t)row * LLn + l] = a;
    }
}

// ---------------------------------------------------------------------------
// K3: ax[bs,h,d] = sum_l attn[bs,h,l]*x[bs,l,d], split to bf16. CTA per bs.
// ---------------------------------------------------------------------------
__global__ __launch_bounds__(256) void ax_kernel(
    const float* __restrict__ x, const float* __restrict__ attn,
    __nv_bfloat16* __restrict__ axh, __nv_bfloat16* __restrict__ axl)
{
    __shared__ __align__(16) float a_s[HHn][LLn];
    const int bs = blockIdx.x;
    const int tid = threadIdx.x;

    ((float4*)a_s)[tid] = ((const float4*)(attn + (size_t)bs * 1024))[tid];
    __syncthreads();

    const int d = tid * 2;
    const float* xp = x + (size_t)bs * LLn * DDn + d;

    u64 acc[HHn][2];
    #pragma unroll
    for (int h = 0; h < HHn; h++) { acc[h][0] = 0ull; acc[h][1] = 0ull; }

    #pragma unroll 4
    for (int l = 0; l < LLn; l += 2) {
        float2 x0 = *(const float2*)(xp + (size_t)l * DDn);
        float2 x1 = *(const float2*)(xp + (size_t)(l + 1) * DDn);
        u64 p0 = pk2(x0.x, x1.x);
        u64 p1 = pk2(x0.y, x1.y);
        #pragma unroll
        for (int h = 0; h < HHn; h++) {
            u64 av = __double_as_longlong(*(const double*)&a_s[h][l]);
            fma2(acc[h][0], av, p0);
            fma2(acc[h][1], av, p1);
        }
    }
    #pragma unroll
    for (int h = 0; h < HHn; h++) {
        float2 s0 = upk2(acc[h][0]);
        float2 s1 = upk2(acc[h][1]);
        float v0 = s0.x + s0.y, v1 = s1.x + s1.y;
        size_t o = ((size_t)bs * HHn + h) * DDn + d;
        __nv_bfloat16 bh, bl;
        bsplit(v0, bh, bl); axh[o] = bh;     axl[o] = bl;
        bsplit(v1, bh, bl); axh[o + 1] = bh; axl[o + 1] = bl;
    }
}

// ---------------------------------------------------------------------------
// HMMA split-bf16 GEMM: C[M,N] = A[M,K] @ B[N,K]^T (+bias,+relu,+res)
// ---------------------------------------------------------------------------
template<int BM, int WM, int WN, bool RELU, bool RES, bool OSPLIT>
__global__ __launch_bounds__(WM*WN*32, 1) void gemm_mma(
    const __nv_bfloat16* __restrict__ Ah, const __nv_bfloat16* __restrict__ Al,
    const __nv_bfloat16* __restrict__ Bh, const __nv_bfloat16* __restrict__ Bl,
    const float* __restrict__ bias, const float* __restrict__ res,
    float* __restrict__ C, __nv_bfloat16* __restrict__ Ch,
    __nv_bfloat16* __restrict__ Cl, int M, int N, int K)
{
    constexpr int BN = BM, BK = 32;
    constexpr int THREADS = WM * WN * 32;
    constexpr int ARR_BYTES = BM * 64;
    constexpr int STAGE = 4 * ARR_BYTES;
    constexpr int MT = (BM / WM) / 16;
    constexpr int NT = (BN / WN) / 8;
    constexpr int CHUNKS = 4 * BM * 4;
    constexpr int CPT = CHUNKS / THREADS;

    extern __shared__ __align__(128) char dsm[];
    const uint32_t sb = smem_u32(dsm);

    const int tid = threadIdx.x, wid = tid >> 5, lane = tid & 31;
    const int bm = blockIdx.y * BM, bn = blockIdx.x * BN;
    const int wm = wid / WN, wn = wid % WN;
    const int KT = K / BK;

    auto load_stage = [&](int kt, int s) {
        const uint32_t base = sb + s * STAGE;
        #pragma unroll
        for (int i = 0; i < CPT; i++) {
            int id = tid + i * THREADS;
            int aid = id / (BM * 4);
            int wthin = id % (BM * 4);
            int row = wthin >> 2;
            int ck = wthin & 3;
            const __nv_bfloat16* g;
            if (aid == 0) g = Ah; else if (aid == 1) g = Al;
            else if (aid == 2) g = Bh; else g = Bl;
            int rowbase = (aid < 2) ? bm : bn;
            const __nv_bfloat16* src =
                g + (size_t)(rowbase + row) * K + (size_t)kt * BK + ck * 8;
            uint32_t dst = base + aid * ARR_BYTES + tile_off(row, ck);
            CPA16(dst, src);
        }
        CPA_COMMIT();
    };

    float c[MT][NT][4];
    #pragma unroll
    for (int i = 0; i < MT; i++)
        #pragma unroll
        for (int j = 0; j < NT; j++)
            #pragma unroll
            for (int q = 0; q < 4; q++) c[i][j][q] = 0.f;

    load_stage(0, 0);
    CPA_WAIT0();
    __syncthreads();

    const int aRow0 = wm * (BM / WM);
    const int bRow0 = wn * (BN / WN);

    for (int kt = 0; kt < KT; kt++) {
        if (kt + 1 < KT) load_stage(kt + 1, (kt + 1) & 1);

        const uint32_t base = sb + (kt & 1) * STAGE;
        const uint32_t sAh = base;
        const uint32_t sAl = base + ARR_BYTES;
        const uint32_t sBh = base + 2 * ARR_BYTES;
        const uint32_t sBl = base + 3 * ARR_BYTES;

        #pragma unroll
        for (int ks = 0; ks < 2; ks++) {
            uint32_t aH[MT][4], aL[MT][4];
            #pragma unroll
            for (int mt = 0; mt < MT; mt++) {
                int row = aRow0 + mt * 16 + (lane & 15);
                int ck = ks * 2 + (lane >> 4);
                uint32_t off = tile_off(row, ck);
                LDSM4(aH[mt], sAh + off);
                LDSM4(aL[mt], sAl + off);
            }
            uint32_t bH[NT][2], bL[NT][2];
            #pragma unroll
            for (int p = 0; p < NT / 2; p++) {
                int row = bRow0 + p * 16 + (lane & 7) + ((lane >> 4) << 3);
                int ck = ks * 2 + ((lane >> 3) & 1);
                uint32_t off = tile_off(row, ck);
                uint32_t r[4];
                LDSM4(r, sBh + off);
                bH[2*p][0] = r[0]; bH[2*p][1] = r[1];
                bH[2*p+1][0] = r[2]; bH[2*p+1][1] = r[3];
                LDSM4(r, sBl + off);
                bL[2*p][0] = r[0]; bL[2*p][1] = r[1];
                bL[2*p+1][0] = r[2]; bL[2*p+1][1] = r[3];
            }
            #pragma unroll
            for (int mt = 0; mt < MT; mt++)
                #pragma unroll
                for (int nt = 0; nt < NT; nt++) {
                    MMA_BF16(c[mt][nt], aH[mt], bH[nt]);
                    MMA_BF16(c[mt][nt], aH[mt], bL[nt]);
                    MMA_BF16(c[mt][nt], aL[mt], bH[nt]);
                }
        }
        CPA_WAIT0();
        __syncthreads();
    }

    #pragma unroll
    for (int mt = 0; mt < MT; mt++) {
        #pragma unroll
        for (int nt = 0; nt < NT; nt++) {
            int row = bm + aRow0 + mt * 16 + (lane >> 2);
            int col = bn + bRow0 + nt * 8 + ((lane & 3) << 1);
            #pragma unroll
            for (int half = 0; half < 2; half++) {
                int r = row + half * 8;
                float v0 = c[mt][nt][half * 2 + 0];
                float v1 = c[mt][nt][half * 2 + 1];
                if (bias) { v0 += bias[col]; v1 += bias[col + 1]; }
                if (RELU) { v0 = fmaxf(v0, 0.f); v1 = fmaxf(v1, 0.f); }
                if (RES) {
                    v0 += res[(size_t)r * N + col];
                    v1 += res[(size_t)r * N + col + 1];
                }
                if (OSPLIT) {
                    __nv_bfloat16 h, l;
                    bsplit(v0, h, l);
                    Ch[(size_t)r * N + col] = h; Cl[(size_t)r * N + col] = l;
                    bsplit(v1, h, l);
                    Ch[(size_t)r * N + col + 1] = h; Cl[(size_t)r * N + col + 1] = l;
                } else {
                    C[(size_t)r * N + col] = v0;
                    C[(size_t)r * N + col + 1] = v1;
                }
            }
        }
    }
}

// ---------------------------------------------------------------------------
// Split fp32 -> (bf16 hi, bf16 lo)
// ---------------------------------------------------------------------------
__global__ __launch_bounds__(256) void split_kernel(
    const float4* __restrict__ in, __nv_bfloat16* __restrict__ hi,
    __nv_bfloat16* __restrict__ lo, int n4)
{
    int i = blockIdx.x * blockDim.x + threadIdx.x;
    if (i >= n4) return;
    float4 v = in[i];
    __nv_bfloat16 h[4], l[4];
    bsplit(v.x, h[0], l[0]); bsplit(v.y, h[1], l[1]);
    bsplit(v.z, h[2], l[2]); bsplit(v.w, h[3], l[3]);
    *(ushort4*)(hi + 4 * (size_t)i) = make_ushort4(
        __bfloat16_as_ushort(h[0]), __bfloat16_as_ushort(h[1]),
        __bfloat16_as_ushort(h[2]), __bfloat16_as_ushort(h[3]));
    *(ushort4*)(lo + 4 * (size_t)i) = make_ushort4(
        __bfloat16_as_ushort(l[0]), __bfloat16_as_ushort(l[1]),
        __bfloat16_as_ushort(l[2]), __bfloat16_as_ushort(l[3]));
}

// ---------------------------------------------------------------------------
// LayerNorm D=512, one CTA/row; optional split bf16 outputs
// ---------------------------------------------------------------------------
__device__ __forceinline__ float block_sum(float v, float* red)
{
    const int lane = threadIdx.x & 31, warp = threadIdx.x >> 5;
    #pragma unroll
    for (int off = 16; off; off >>= 1)
        v += __shfl_xor_sync(0xffffffffu, v, off);
    if (lane == 0) red[warp] = v;
    __syncthreads();
    if (warp == 0) {
        float s = (lane < 8) ? red[lane] : 0.f;
        #pragma unroll
        for (int off = 4; off; off >>= 1)
            s += __shfl_xor_sync(0xffffffffu, s, off);
        if (lane == 0) red[0] = s;
    }
    __syncthreads();
    float rv = red[0];
    __syncthreads();
    return rv;
}

template<bool SPLIT>
__global__ __launch_bounds__(256) void ln_kernel(
    const float* __restrict__ in, const float* __restrict__ g,
    const float* __restrict__ b, float* __restrict__ out,
    __nv_bfloat16* __restrict__ oh, __nv_bfloat16* __restrict__ ol)
{
    __shared__ float red[8];
    const int row = blockIdx.x, tid = threadIdx.x;
    const float* r = in + (size_t)row * DDn;
    float v0 = r[tid], v1 = r[tid + 256];
    float mu = block_sum(v0 + v1, red) * (1.f / DDn);
    float e0 = v0 - mu, e1 = v1 - mu;
    float var = block_sum(e0 * e0 + e1 * e1, red) * (1.f / DDn);
    float inv = rsqrtf(var + 1e-6f);
    float y0 = e0 * inv * g[tid] + b[tid];
    float y1 = e1 * inv * g[tid + 256] + b[tid + 256];
    size_t i0 = (size_t)row * DDn + tid, i1 = i0 + 256;
    out[i0] = y0; out[i1] = y1;
    if (SPLIT) {
        __nv_bfloat16 h, l;
        bsplit(y0, h, l); oh[i0] = h; ol[i0] = l;
        bsplit(y1, h, l); oh[i1] = h; ol[i1] = l;
    }
}

// ---------------------------------------------------------------------------
extern "C" void kernel_launch(void* const* d_in, const int* in_sizes, int n_in,
                              void* d_out, int out_size)
{
    const float* x    = (const float*)d_in[0];
    const int*   mask = (const int*)  d_in[1];
    const float* w    = (const float*)d_in[2];
    const float* v_w  = (const float*)d_in[3];
    const float* ln_g = (const float*)d_in[4];
    const float* ln_b = (const float*)d_in[5];
    const float* w1   = (const float*)d_in[6];
    const float* b1   = (const float*)d_in[7];
    const float* w2   = (const float*)d_in[8];
    const float* b2   = (const float*)d_in[9];
    const float* fg   = (const float*)d_in[10];
    const float* fb   = (const float*)d_in[11];

    float *t, *o, *lg, *at;
    __nv_bfloat16 *axh, *axl, *oh, *ol, *hh, *hl;
    __nv_bfloat16 *vwh, *vwl, *w1h, *w1l, *w2h, *w2l;
    cudaGetSymbolAddress((void**)&t,   g_t);
    cudaGetSymbolAddress((void**)&o,   g_o);
    cudaGetSymbolAddress((void**)&lg,  g_logits);
    cudaGetSymbolAddress((void**)&at,  g_attn);
    cudaGetSymbolAddress((void**)&axh, g_axh);
    cudaGetSymbolAddress((void**)&axl, g_axl);
    cudaGetSymbolAddress((void**)&oh,  g_oh);
    cudaGetSymbolAddress((void**)&ol,  g_ol);
    cudaGetSymbolAddress((void**)&hh,  g_hh);
    cudaGetSymbolAddress((void**)&hl,  g_hl);
    cudaGetSymbolAddress((void**)&vwh, g_vwh);
    cudaGetSymbolAddress((void**)&vwl, g_vwl);
    cudaGetSymbolAddress((void**)&w1h, g_w1h);
    cudaGetSymbolAddress((void**)&w1l, g_w1l);
    cudaGetSymbolAddress((void**)&w2h, g_w2h);
    cudaGetSymbolAddress((void**)&w2l, g_w2l);

    float* y_out = (float*)d_out;
    float* attn_out = (out_size >= NROW * DDn + NROW * LLn)
                        ? (y_out + NROW * DDn) : nullptr;

    constexpr int SM128 = 2 * 4 * 128 * 64;  // 65536
    constexpr int SM64  = 2 * 4 * 64 * 64;   // 32768
    cudaFuncSetAttribute(gemm_mma<64, 2, 2, false, false, false>,
                         cudaFuncAttributeMaxDynamicSharedMemorySize, SM64);
    cudaFuncSetAttribute(gemm_mma<128, 2, 4, true, false, true>,
                         cudaFuncAttributeMaxDynamicSharedMemorySize, SM128);
    cudaFuncSetAttribute(gemm_mma<64, 2, 2, false, true, false>,
                         cudaFuncAttributeMaxDynamicSharedMemorySize, SM64);

    // split weights to bf16 hi/lo
    split_kernel<<<(DDn*DDn/4 + 255)/256, 256>>>(
        (const float4*)v_w, vwh, vwl, DDn*DDn/4);
    split_kernel<<<(DIn*DDn/4 + 255)/256, 256>>>(
        (const float4*)w1, w1h, w1l, DIn*DDn/4);
    split_kernel<<<(DDn*DIn/4 + 255)/256, 256>>>(
        (const float4*)w2, w2h, w2l, DDn*DIn/4);

    // attention: logits -> softmax -> attn@x
    logits_kernel<<<LLn, 256>>>(x, w, lg);
    softmax_kernel<<<NROW/8, 256>>>(lg, mask, at, attn_out);
    ax_kernel<<<NBS, 256>>>(x, at, axh, axl);

    // t = ax @ v_w^T   (1024 x 512 x 512)
    gemm_mma<64, 2, 2, false, false, false>
        <<<dim3(DDn/64, NROW/64), 128, SM64>>>(
        axh, axl, vwh, vwl, nullptr, nullptr, t, nullptr, nullptr,
        NROW, DDn, DDn);

    // o = LN(t) (+ split)
    ln_kernel<true><<<NROW, 256>>>(t, ln_g, ln_b, o, oh, ol);

    // h = relu(o @ w1^T + b1)  (1024 x 2048 x 512)
    gemm_mma<128, 2, 4, true, false, true>
        <<<dim3(DIn/128, NROW/128), 256, SM128>>>(
        oh, ol, w1h, w1l, b1, nullptr, nullptr, hh, hl,
        NROW, DIn, DDn);

    // t = h @ w2^T + b2 + o  (1024 x 512 x 2048)
    gemm_mma<64, 2, 2, false, true, false>
        <<<dim3(DDn/64, NROW/64), 128, SM64>>>(
        hh, hl, w2h, w2l, b2, o, t, nullptr, nullptr,
        NROW, DDn, DIn);

    // y = LN(t)
    ln_kernel<false><<<NROW, 256>>>(t, fg, fb, y_out, nullptr, nullptr);
}